// round 14
// baseline (speedup 1.0000x reference)
#include <cuda_runtime.h>
#include <math.h>

// Problem shapes (fixed by dataset)
#define SS 2048
#define BB 32
#define HH 1024

#define GRID 148   // persistent co-resident blocks, all phases
#define NOB 64     // o-chunks of 16
#define OC  16

// Scratch (static __device__ — no allocations allowed)
__device__ float g_u_part[NOB][BB * HH];  // 8 MB (L2-resident)
__device__ float g_u[BB * HH];            // 128 KB
__device__ float g_scores[BB * SS];       // 256 KB
__device__ unsigned g_bar[3];             // grid-barrier counters

// ---------------------------------------------------------------------------
// Grid barrier among GRID co-resident blocks (t==0 arrives/spins, others
// park at __syncthreads). Counters zeroed per launch by a captured memset.
// ---------------------------------------------------------------------------
__device__ __forceinline__ void grid_barrier(int id) {
    __syncthreads();
    if (threadIdx.x == 0) {
        __threadfence();                       // release
        atomicAdd(&g_bar[id], 1u);
        while (atomicAdd(&g_bar[id], 0u) < GRID) __nanosleep(32);
        __threadfence();                       // acquire
    }
    __syncthreads();
}

// ---------------------------------------------------------------------------
// ONE persistent kernel, 148 x 1024. All blocks work in every phase (the
// R5 fusion failure had 116 blocks idle through long phases — avoided here).
//   U: 128 blocks x one (o-chunk, b-half) tile of u_part   (~2us, balanced)
//   R: all 148 blocks reduce contiguous coalesced output ranges (~1us)
//   S: scores, static s-interleave (best-known R9 loop, untouched)
//   M: softmax, blocks 0..31
// ---------------------------------------------------------------------------
__global__ void __launch_bounds__(1024, 1)
k_all(const float* __restrict__ hidden, const float* __restrict__ enc,
      const float* __restrict__ W, float* __restrict__ out) {
    const int blk  = blockIdx.x;
    const int t    = threadIdx.x;
    const int warp = t >> 5;
    const int lane = t & 31;

    __shared__ float hs[OC * 16];
    __shared__ float red[32];

    // ---- Phase U: u_part tiles (128 working blocks) ----
    if (blk < NOB * 2) {
        const int j = blk >> 1;          // o-chunk
        const int half = blk & 1;        // b-half
        const int o0 = j * OC;
        const int bbase = half * 16;
        const int h = t;                 // 0..1023

        if (t < OC * 16) {
            int o = t >> 4, bl = t & 15;
            hs[t] = hidden[(bbase + bl) * HH + o0 + o];
        }
        __syncthreads();

        float w[OC];
#pragma unroll
        for (int o = 0; o < OC; ++o)
            w[o] = W[(size_t)(o0 + o) * HH + h];

        float acc[16];
#pragma unroll
        for (int bl = 0; bl < 16; ++bl) acc[bl] = 0.f;

        const float4* hs4 = reinterpret_cast<const float4*>(hs);
#pragma unroll
        for (int o = 0; o < OC; ++o) {
#pragma unroll
            for (int q = 0; q < 4; ++q) {
                float4 hv = hs4[o * 4 + q];   // warp-broadcast LDS.128
                acc[q * 4 + 0] = fmaf(hv.x, w[o], acc[q * 4 + 0]);
                acc[q * 4 + 1] = fmaf(hv.y, w[o], acc[q * 4 + 1]);
                acc[q * 4 + 2] = fmaf(hv.z, w[o], acc[q * 4 + 2]);
                acc[q * 4 + 3] = fmaf(hv.w, w[o], acc[q * 4 + 3]);
            }
        }

#pragma unroll
        for (int bl = 0; bl < 16; ++bl)
            g_u_part[j][(bbase + bl) * HH + h] = acc[bl];
    }
    grid_barrier(0);

    // ---- Phase R: reduce partials, contiguous per-block ranges ----
    // 32768 outputs = 60 blocks * 222 + 88 blocks * 221; coalesced.
    {
        int ofs, cnt;
        if (blk < 60) { ofs = blk * 222; cnt = 222; }
        else          { ofs = 60 * 222 + (blk - 60) * 221; cnt = 221; }
        if (t < cnt) {
            const int i = ofs + t;
            float s = 0.f;
#pragma unroll 8
            for (int p = 0; p < NOB; ++p) s += g_u_part[p][i];
            g_u[i] = s;
        }
    }
    grid_barrier(1);

    // ---- Phase S: scores, static s-interleave, no syncs ----
    {
        const int b = warp;
        const float4* ub = reinterpret_cast<const float4*>(g_u + b * HH);
        float4 u[8];
#pragma unroll
        for (int c = 0; c < 8; ++c) u[c] = ub[c * 32 + lane];

        for (int s = blk; s < SS; s += GRID) {
            const float4* r =
                reinterpret_cast<const float4*>(enc + ((size_t)s * BB + b) * HH);
            float a = 0.f;
#pragma unroll
            for (int c = 0; c < 8; ++c) {
                float4 e = __ldcs(&r[c * 32 + lane]);
                a += e.x * u[c].x + e.y * u[c].y + e.z * u[c].z + e.w * u[c].w;
            }
#pragma unroll
            for (int off = 16; off; off >>= 1)
                a += __shfl_xor_sync(0xFFFFFFFFu, a, off);
            if (lane == 0) g_scores[b * SS + s] = a;
        }
    }
    grid_barrier(2);

    // ---- Phase M: softmax (blocks 0..31, batch bb = blk) ----
    if (blk < BB) {
        const int bb = blk;
        float v0 = g_scores[bb * SS + t];
        float v1 = g_scores[bb * SS + t + 1024];

        float m = fmaxf(v0, v1);
#pragma unroll
        for (int off = 16; off; off >>= 1)
            m = fmaxf(m, __shfl_xor_sync(0xFFFFFFFFu, m, off));
        if (lane == 0) red[warp] = m;
        __syncthreads();
        if (warp == 0) {
            float x = red[lane];
#pragma unroll
            for (int off = 16; off; off >>= 1)
                x = fmaxf(x, __shfl_xor_sync(0xFFFFFFFFu, x, off));
            if (lane == 0) red[0] = x;
        }
        __syncthreads();
        const float bm = red[0];
        __syncthreads();  // before reusing red[]

        v0 = __expf(v0 - bm);
        v1 = __expf(v1 - bm);
        float s = v0 + v1;
#pragma unroll
        for (int off = 16; off; off >>= 1)
            s += __shfl_xor_sync(0xFFFFFFFFu, s, off);
        if (lane == 0) red[warp] = s;
        __syncthreads();
        if (warp == 0) {
            float x = red[lane];
#pragma unroll
            for (int off = 16; off; off >>= 1)
                x += __shfl_xor_sync(0xFFFFFFFFu, x, off);
            if (lane == 0) red[0] = x;
        }
        __syncthreads();
        const float inv = 1.f / red[0];

        out[bb * SS + t]        = v0 * inv;
        out[bb * SS + t + 1024] = v1 * inv;
    }
}

// ---------------------------------------------------------------------------
// Inputs (metadata order): hidden [B,H], encoder_outputs [S,B,H], W [H,H], b [H]
// The bias input is mathematically irrelevant (softmax shift invariance).
// ---------------------------------------------------------------------------
extern "C" void kernel_launch(void* const* d_in, const int* in_sizes, int n_in,
                              void* d_out, int out_size) {
    const float* hidden = (const float*)d_in[0];
    const float* enc    = (const float*)d_in[1];
    const float* W      = (const float*)d_in[2];
    float* out          = (float*)d_out;

    // Zero the barrier counters each invocation (captured as a graph node).
    void* bar_ptr;
    cudaGetSymbolAddress(&bar_ptr, g_bar);
    cudaMemsetAsync(bar_ptr, 0, sizeof(unsigned) * 3);

    k_all<<<GRID, 1024>>>(hidden, enc, W, out);
}